// round 8
// baseline (speedup 1.0000x reference)
#include <cuda_runtime.h>
#include <cstdint>

// ---------------------------------------------------------------------------
// Problem constants
// ---------------------------------------------------------------------------
#define EMBED   1024
#define NHEADS  16
#define HDIM    64
#define NBATCH  2
#define SEQ     2048
#define TOKENS  (NBATCH * SEQ)          // 4096
#define WELEMS  (EMBED * EMBED)         // 1048576
#define SCALE_ATTN 0.125f               // 1/sqrt(64)
#define SA 44                           // GEMM smem row stride (floats)

// Flash-attention tiling
#define BQ   128
#define BKV  64
#define NJ   (SEQ / BKV)                // 32
#define SQ8  68                         // flash smem row stride (64 + 4)

// In-octet interleave: logical index l -> physical ((l&3)<<1)|((l&7)>>2)
// (pairs (t, t+4) become adjacent, enabling float2 fragment loads)
#define OCT_PERM(l) (((l) & ~7) | ((((l) & 3) << 1) | ((((l) & 7)) >> 2)))

// ---------------------------------------------------------------------------
// Scratch (static __device__ globals; no runtime allocation allowed)
// ---------------------------------------------------------------------------
__device__ float g_Wdq[4 * WELEMS];                                  // tf32-rounded dequant weights
__device__ int   g_absmax[4];
__device__ float g_Xin[3 * (size_t)TOKENS * EMBED];                  // tf32-rounded inputs
__device__ float g_Q[(size_t)NBATCH * NHEADS * SEQ * HDIM];          // [B,H,S,Dperm]
__device__ float g_K[(size_t)NBATCH * NHEADS * SEQ * HDIM];          // [B,H,S,Dperm]
__device__ float g_V[(size_t)NBATCH * NHEADS * SEQ * HDIM];          // [B,H,S,D] natural
__device__ float g_Vt[(size_t)NBATCH * NHEADS * HDIM * SEQ];         // [B,H,D,Sperm]
__device__ float g_ctx[(size_t)TOKENS * EMBED];                      // [B,S,E]

// ---------------------------------------------------------------------------
// Helpers (target-portable PTX only: mma.sync sm_80+, cp.async sm_80+)
// ---------------------------------------------------------------------------
__device__ __forceinline__ uint32_t smem_u32(const void* p) {
    uint32_t a;
    asm("{ .reg .u64 t; cvta.to.shared.u64 t, %1; cvt.u32.u64 %0, t; }" : "=r"(a) : "l"(p));
    return a;
}

__device__ __forceinline__ float rna_tf32(float x) {
    float r;
    asm("cvt.rna.tf32.f32 %0, %1;" : "=f"(r) : "f"(x));
    return r;
}

__device__ __forceinline__ void cp_async16(uint32_t saddr, const void* gaddr) {
    asm volatile("cp.async.cg.shared.global [%0], [%1], 16;"
                 :: "r"(saddr), "l"(gaddr) : "memory");
}

__device__ __forceinline__ void mma_tf32(float* d, const uint32_t* a, const uint32_t* b) {
    asm volatile(
        "mma.sync.aligned.m16n8k8.row.col.f32.tf32.tf32.f32 "
        "{%0,%1,%2,%3}, {%4,%5,%6,%7}, {%8,%9}, {%0,%1,%2,%3};"
        : "+f"(d[0]), "+f"(d[1]), "+f"(d[2]), "+f"(d[3])
        : "r"(a[0]), "r"(a[1]), "r"(a[2]), "r"(a[3]), "r"(b[0]), "r"(b[1]));
}

// ---------------------------------------------------------------------------
// Weight quantization (bit-faithful: s = max|W|/127, round-half-even, clip,
// dequantize), then RNA-round to tf32 so the MMA truncation is lossless.
// ---------------------------------------------------------------------------
__global__ void k_reset() { if (threadIdx.x < 4) g_absmax[threadIdx.x] = 0; }

__global__ void k_absmax(const float* __restrict__ w0, const float* __restrict__ w1,
                         const float* __restrict__ w2, const float* __restrict__ w3)
{
    const float* W = (blockIdx.y == 0) ? w0 : (blockIdx.y == 1) ? w1
                   : (blockIdx.y == 2) ? w2 : w3;
    float m = 0.0f;
    for (int i = blockIdx.x * blockDim.x + threadIdx.x; i < WELEMS;
         i += gridDim.x * blockDim.x)
        m = fmaxf(m, fabsf(W[i]));
    #pragma unroll
    for (int o = 16; o; o >>= 1) m = fmaxf(m, __shfl_xor_sync(0xffffffffu, m, o));
    if ((threadIdx.x & 31) == 0) atomicMax(&g_absmax[blockIdx.y], __float_as_int(m));
}

__global__ void k_dequant(const float* __restrict__ w0, const float* __restrict__ w1,
                          const float* __restrict__ w2, const float* __restrict__ w3)
{
    int sel = blockIdx.y;
    const float* W = (sel == 0) ? w0 : (sel == 1) ? w1 : (sel == 2) ? w2 : w3;
    float s = __int_as_float(g_absmax[sel]) / 127.0f;
    int i = (blockIdx.x * blockDim.x + threadIdx.x) * 4;
    float4 w = *(const float4*)&W[i];
    float4 r;
    r.x = rna_tf32(fminf(fmaxf(rintf(w.x / s), -128.0f), 127.0f) * s);
    r.y = rna_tf32(fminf(fmaxf(rintf(w.y / s), -128.0f), 127.0f) * s);
    r.z = rna_tf32(fminf(fmaxf(rintf(w.z / s), -128.0f), 127.0f) * s);
    r.w = rna_tf32(fminf(fmaxf(rintf(w.w / s), -128.0f), 127.0f) * s);
    *(float4*)&g_Wdq[(size_t)sel * WELEMS + i] = r;
}

__global__ void k_cvt_in(const float* __restrict__ q, const float* __restrict__ k,
                         const float* __restrict__ v)
{
    int sel = blockIdx.y;
    const float* s = (sel == 0) ? q : (sel == 1) ? k : v;
    float* d = g_Xin + (size_t)sel * TOKENS * EMBED;
    int i = (blockIdx.x * blockDim.x + threadIdx.x) * 4;
    float4 w = *(const float4*)&s[i];
    w.x = rna_tf32(w.x); w.y = rna_tf32(w.y);
    w.z = rna_tf32(w.z); w.w = rna_tf32(w.w);
    *(float4*)&d[i] = w;
}

// ---------------------------------------------------------------------------
// Tensor-core tf32 NT GEMM via mma.sync.m16n8k8:
//   C[M, N] = alpha * A[M,K] * B[N,K]^T (+ bias)
// MODE 0: plain row-major out
// MODE 1: QKV scatter to [B,H,S,D] natural, +bias, RNA-rounded (V)
// MODE 3: like MODE 1 but with in-octet d interleave (Q, K)
// ---------------------------------------------------------------------------
template <int BN, int NT, int MODE>
__global__ __launch_bounds__(NT, 2)
void gemm_mma(const float* __restrict__ A, const float* __restrict__ B,
              const float* __restrict__ bias, float* __restrict__ C,
              int K, long long aZ, long long bZ, float alpha, long long cZ, int ldc)
{
    extern __shared__ float smem[];
    constexpr int STF = (128 + BN) * SA;

    const int tid  = threadIdx.x;
    const int wid  = tid >> 5, lane = tid & 31;
    const int wm   = wid & 1, wn = wid >> 1;
    const int qid  = lane >> 2, tig = lane & 3;

    const float* gA = A + (long long)blockIdx.z * aZ + (size_t)(blockIdx.y * 128) * K;
    const float* gB = B + (long long)blockIdx.z * bZ + (size_t)(blockIdx.x * BN) * K;

    float acc[4][4][4] = {};

    auto loadStage = [&](int s, int k0) {
        float* sAp = smem + s * STF;
        float* sBp = sAp + 128 * SA;
        const int r0 = tid >> 3, c = (tid & 7) * 4;
        #pragma unroll
        for (int it = 0; it < 128 * 8 / NT; ++it) {
            const int r = r0 + it * (NT / 8);
            cp_async16(smem_u32(sAp + r * SA + c), gA + (size_t)r * K + k0 + c);
        }
        #pragma unroll
        for (int it = 0; it < BN * 8 / NT; ++it) {
            const int r = r0 + it * (NT / 8);
            cp_async16(smem_u32(sBp + r * SA + c), gB + (size_t)r * K + k0 + c);
        }
        asm volatile("cp.async.commit_group;" ::: "memory");
    };

    const int ns = K / 32;
    loadStage(0, 0);
    for (int i = 0; i < ns; ++i) {
        if (i + 1 < ns) {
            loadStage((i + 1) & 1, (i + 1) * 32);
            asm volatile("cp.async.wait_group 1;" ::: "memory");
        } else {
            asm volatile("cp.async.wait_group 0;" ::: "memory");
        }
        __syncthreads();

        const float* sAp = smem + (i & 1) * STF;
        const float* sBp = sAp + 128 * SA;
        #pragma unroll
        for (int ks = 0; ks < 4; ++ks) {
            const int k = ks * 8 + tig;
            uint32_t af[4][4], bf[4][2];
            #pragma unroll
            for (int mt = 0; mt < 4; ++mt) {
                const float* ap = sAp + (wm * 64 + mt * 16 + qid) * SA + k;
                af[mt][0] = __float_as_uint(ap[0]);
                af[mt][1] = __float_as_uint(ap[8 * SA]);
                af[mt][2] = __float_as_uint(ap[4]);
                af[mt][3] = __float_as_uint(ap[8 * SA + 4]);
            }
            #pragma unroll
            for (int nt = 0; nt < 4; ++nt) {
                const float* bp = sBp + (wn * 32 + nt * 8 + qid) * SA + k;
                bf[nt][0] = __float_as_uint(bp[0]);
                bf[nt][1] = __float_as_uint(bp[4]);
            }
            #pragma unroll
            for (int mt = 0; mt < 4; ++mt)
                #pragma unroll
                for (int nt = 0; nt < 4; ++nt)
                    mma_tf32(acc[mt][nt], af[mt], bf[nt]);
        }
        __syncthreads();
    }

    const int z = blockIdx.z;
    #pragma unroll
    for (int mt = 0; mt < 4; ++mt) {
        const int m = blockIdx.y * 128 + wm * 64 + mt * 16 + qid;
        #pragma unroll
        for (int nt = 0; nt < 4; ++nt) {
            const int n = blockIdx.x * BN + wn * 32 + nt * 8 + tig * 2;
            float c0 = acc[mt][nt][0], c1 = acc[mt][nt][1];
            float c2 = acc[mt][nt][2], c3 = acc[mt][nt][3];

            if (MODE == 0) {
                c0 *= alpha; c1 *= alpha; c2 *= alpha; c3 *= alpha;
                if (bias) {
                    const float b0 = bias[n], b1 = bias[n + 1];
                    c0 += b0; c1 += b1; c2 += b0; c3 += b1;
                }
                float* p0 = C + (long long)z * cZ + (size_t)m * ldc + n;
                float* p1 = C + (long long)z * cZ + (size_t)(m + 8) * ldc + n;
                *(float2*)p0 = make_float2(c0, c1);
                *(float2*)p1 = make_float2(c2, c3);
            } else if (MODE == 1) {
                const int b = m >> 11, s2 = m & (SEQ - 1);
                const int h = n >> 6, d = n & (HDIM - 1);
                const float b0 = bias[n], b1 = bias[n + 1];
                c0 = rna_tf32(c0 + b0); c1 = rna_tf32(c1 + b1);
                c2 = rna_tf32(c2 + b0); c3 = rna_tf32(c3 + b1);
                const size_t base = ((size_t)b * NHEADS + h) * SEQ;
                *(float2*)&C[(base + s2) * HDIM + d]     = make_float2(c0, c1);
                *(float2*)&C[(base + s2 + 8) * HDIM + d] = make_float2(c2, c3);
            } else {  // MODE 3: interleaved d
                const int b = m >> 11, s2 = m & (SEQ - 1);
                const int h = n >> 6;
                const int d0i = n & (HDIM - 1);
                const int p0 = OCT_PERM(d0i);
                const int p1 = OCT_PERM(d0i + 1);
                const float b0 = bias[n], b1 = bias[n + 1];
                c0 = rna_tf32(c0 + b0); c1 = rna_tf32(c1 + b1);
                c2 = rna_tf32(c2 + b0); c3 = rna_tf32(c3 + b1);
                const size_t base = ((size_t)b * NHEADS + h) * SEQ;
                C[(base + s2) * HDIM + p0]     = c0;
                C[(base + s2) * HDIM + p1]     = c1;
                C[(base + s2 + 8) * HDIM + p0] = c2;
                C[(base + s2 + 8) * HDIM + p1] = c3;
            }
        }
    }
}

// ---------------------------------------------------------------------------
// V transpose: [BH,S,64] -> [BH,64,Sperm]  (s interleaved per octet so the
// flash PV B-fragment (k, k+4) pair is a single float2 load)
// ---------------------------------------------------------------------------
__global__ void k_transpose_v(const float* __restrict__ V, float* __restrict__ Vt)
{
    __shared__ float t[32][33];
    const int bh = blockIdx.z;
    const int s0 = blockIdx.x * 32, d0 = blockIdx.y * 32;
    const float* src = V + (size_t)bh * SEQ * HDIM;
    float* dst = Vt + (size_t)bh * HDIM * SEQ;
    const int x = threadIdx.x, y = threadIdx.y;    // 32 x 8
    #pragma unroll
    for (int i = 0; i < 32; i += 8)
        t[y + i][x] = src[(size_t)(s0 + y + i) * HDIM + d0 + x];
    __syncthreads();
    const int colp = (s0 + x & ~7) | ((((x & 3) << 1) | ((x & 7) >> 2)));
    #pragma unroll
    for (int i = 0; i < 32; i += 8)
        dst[(size_t)(d0 + y + i) * SEQ + colp] = t[x][y + i];
}

// ---------------------------------------------------------------------------
// Fused flash attention, v3: permuted layouts.
//  - K tile rows loaded key-permuted (physical p holds logical key
//    (p>>1)+((p&1)<<2)) so the S C-frag IS the P·V A-frag (register rename,
//    no shuffles).
//  - Q/K gmem d-interleaved and Vt s-interleaved so every fragment (k, k+4)
//    pair is one float2 LDS (halves LDS instruction count).
// ---------------------------------------------------------------------------
__global__ __launch_bounds__(256, 2)
void k_flash(const float* __restrict__ Qg, const float* __restrict__ Kg,
             const float* __restrict__ Vtg, float* __restrict__ ctx)
{
    extern __shared__ float sm[];
    float* Qs = sm;                       // 128 x SQ8
    float* Ks = Qs + BQ * SQ8;            // 2 x 64 x SQ8   [key_perm][d_perm]
    float* Vs = Ks + 2 * BKV * SQ8;       // 2 x 64 x SQ8   [d][s_perm]

    const int tid = threadIdx.x;
    const int wid = tid >> 5, lane = tid & 31;
    const int qid = lane >> 2, tig = lane & 3;
    const int bh = blockIdx.z;
    const int b = bh >> 4, h = bh & 15;

    const float* gQ = Qg + ((size_t)bh * SEQ + blockIdx.x * BQ) * HDIM;
    const float* gK = Kg + (size_t)bh * SEQ * HDIM;
    const float* gV = Vtg + (size_t)bh * HDIM * SEQ;

    // Q tile load (own group)
    #pragma unroll
    for (int it = 0; it < 8; ++it) {
        int lin = tid + it * 256;              // 0..2047 -> 128 rows x 16 float4
        int r = lin >> 4, c = (lin & 15) * 4;
        cp_async16(smem_u32(Qs + r * SQ8 + c), gQ + (size_t)r * HDIM + c);
    }
    asm volatile("cp.async.commit_group;" ::: "memory");

    auto loadKV = [&](int j, int buf) {
        float* kd = Ks + buf * BKV * SQ8;
        float* vd = Vs + buf * HDIM * SQ8;
        #pragma unroll
        for (int it = 0; it < 4; ++it) {
            int lin = tid + it * 256;          // 0..1023 -> 64 rows x 16 float4
            int r = lin >> 4, c = (lin & 15) * 4;
            // physical row r holds logical key (r>>1 & 3) + ((r&1)<<2) in-octet
            int rsrc = (r & ~7) | (((r & 7) >> 1) | ((r & 1) << 2));
            cp_async16(smem_u32(kd + r * SQ8 + c), gK + (size_t)(j * BKV + rsrc) * HDIM + c);
            cp_async16(smem_u32(vd + r * SQ8 + c), gV + (size_t)r * SEQ + j * BKV + c);
        }
        asm volatile("cp.async.commit_group;" ::: "memory");
    };

    loadKV(0, 0);

    float mrow0 = -1e30f, mrow1 = -1e30f;
    float lrow0 = 0.0f, lrow1 = 0.0f;
    float o[8][4] = {};
    const int rq = wid * 16 + qid;             // warp-private row (and +8)

    for (int j = 0; j < NJ; ++j) {
        if (j + 1 < NJ) {
            loadKV(j + 1, (j + 1) & 1);
            asm volatile("cp.async.wait_group 1;" ::: "memory");
        } else {
            asm volatile("cp.async.wait_group 0;" ::: "memory");
        }
        __syncthreads();                       // tile j visible to all warps

        // ---- S = Q K^T : float2 fragment loads (d-interleaved layouts) ----
        float s[8][4] = {};
        const float* kb = Ks + (j & 1) * BKV * SQ8;
        #pragma unroll
        for (int ks = 0; ks < 8; ++ks) {
            const int kcol = ks * 8 + tig * 2;     // phys col of (k, k+4) pair
            uint32_t af[4];
            const float2 aq0 = *(const float2*)&Qs[rq * SQ8 + kcol];
            const float2 aq1 = *(const float2*)&Qs[(rq + 8) * SQ8 + kcol];
            af[0] = __float_as_uint(aq0.x);
            af[1] = __float_as_uint(aq1.x);
            af[2] = __float_as_uint(aq0.y);
            af[3] = __float_as_uint(aq1.y);
            #pragma unroll
            for (int nt = 0; nt < 8; ++nt) {
                const float2 bb = *(const float2*)&kb[(nt * 8 + qid) * SQ8 + kcol];
                uint32_t bf[2] = {__float_as_uint(bb.x), __float_as_uint(bb.y)};
                mma_tf32(s[nt], af, bf);
            }
        }

        // ---- online softmax (rows rq and rq+8), P kept in s[][] ----
        // (physical column order is a key permutation; reductions are
        //  order-independent)
        float mx0 = -1e30f, mx1 = -1e30f;
        #pragma unroll
        for (int nt = 0; nt < 8; ++nt) {
            s[nt][0] *= SCALE_ATTN; s[nt][1] *= SCALE_ATTN;
            s[nt][2] *= SCALE_ATTN; s[nt][3] *= SCALE_ATTN;
            mx0 = fmaxf(mx0, fmaxf(s[nt][0], s[nt][1]));
            mx1 = fmaxf(mx1, fmaxf(s[nt][2], s[nt][3]));
        }
        mx0 = fmaxf(mx0, __shfl_xor_sync(0xffffffffu, mx0, 1));
        mx0 = fmaxf(mx0, __shfl_xor_sync(0xffffffffu, mx0, 2));
        mx1 = fmaxf(mx1, __shfl_xor_sync(0xffffffffu, mx1, 1));
        mx1 = fmaxf(mx1, __shfl_xor_sync(0xffffffffu, mx1, 2));
        const float mn0 = fmaxf(mrow0, mx0), mn1 = fmaxf(mrow1, mx1);
        const float a0 = __expf(mrow0 - mn0), a1 = __expf(mrow1 - mn1);
        mrow0 = mn0; mrow1 = mn1;

        float sum0 = 0.0f, sum1 = 0.0f;
        #pragma unroll
        for (int nt = 0; nt < 8; ++nt) {
            const float p0 = __expf(s[nt][0] - mn0), p1 = __expf(s[nt][1] - mn0);
            const float p2 = __expf(s[nt][2] - mn1), p3 = __expf(s[nt][3] - mn1);
            sum0 += p0 + p1; sum1 += p2 + p3;
            s[nt][0] = rna_tf32(p0); s[nt][1] = rna_tf32(p1);
            s[nt][2] = rna_tf32(p2); s[nt][3] = rna_tf32(p3);
        }
        sum0 += __shfl_xor_sync(0xffffffffu, sum0, 1);
        sum0 += __shfl_xor_sync(0xffffffffu, sum0, 2);
        sum1 += __shfl_xor_sync(0xffffffffu, sum1, 1);
        sum1 += __shfl_xor_sync(0xffffffffu, sum1, 2);
        lrow0 = lrow0 * a0 + sum0;
        lrow1 = lrow1 * a1 + sum1;
        #pragma unroll
        for (int nt = 0; nt < 8; ++nt) {
            o[nt][0] *= a0; o[nt][1] *= a0;
            o[nt][2] *= a1; o[nt][3] *= a1;
        }

        // ---- O += P V : A-frag IS the C-frag (key permutation makes
        //      C slots {2t,2t+1} = logical keys {t, t+4}); B via float2 ----
        const float* vb = Vs + (j & 1) * HDIM * SQ8;
        #pragma unroll
        for (int kc = 0; kc < 8; ++kc) {
            uint32_t af[4];
            af[0] = __float_as_uint(s[kc][0]);   // (row rq,   k=tig)
            af[1] = __float_as_uint(s[kc][2]);   // (row rq+8, k=tig)
            af[2] = __float_as_uint(s[kc][1]);   // (row rq,   k=tig+4)
            af[3] = __float_as_uint(s[kc][3]);   // (row rq+8, k=tig+4)
            const int kcol = kc * 8 + tig * 2;
            #pragma unroll
            for (int nt = 0; nt < 8; ++nt) {
                const float2 bb = *(const float2*)&vb[(nt * 8 + qid) * SQ8 + kcol];
                uint32_t bf[2] = {__float_as_uint(bb.x), __float_as_uint(bb.y)};
                mma_tf32(o[nt], af, bf);
            }
        }
        __syncthreads();                       // all reads done before next prefetch lands
    }

    // ---- epilogue: O /= l, RNA-round (feeds out-proj tf32 mma), write ctx ----
    const float inv0 = 1.0f / lrow0, inv1 = 1.0f / lrow1;
    const int q0 = blockIdx.x * BQ + rq;
    float* dst0 = ctx + ((size_t)b * SEQ + q0) * EMBED + h * HDIM;
    float* dst1 = ctx + ((size_t)b * SEQ + q0 + 8) * EMBED + h * HDIM;
    #pragma unroll
    for (int nt = 0; nt < 8; ++nt) {
        const int d = nt * 8 + tig * 2;
        *(float2*)&dst0[d] = make_float2(rna_tf32(o[nt][0] * inv0),
                                         rna_tf32(o[nt][1] * inv0));
        *(float2*)&dst1[d] = make_float2(rna_tf32(o[nt][2] * inv1),
                                         rna_tf32(o[nt][3] * inv1));
    }
}

// ---------------------------------------------------------------------------
// Launch
// ---------------------------------------------------------------------------
#define SMEM_128   ((128 + 128) * SA * 4 * 2)              // 90112 B
#define SMEM_FLASH ((BQ + 2 * BKV + 2 * HDIM) * SQ8 * 4)   // 104448 B -> 2 CTAs/SM

extern "C" void kernel_launch(void* const* d_in, const int* in_sizes, int n_in,
                              void* d_out, int out_size)
{
    (void)in_sizes; (void)n_in; (void)out_size;
    const float* query = (const float*)d_in[0];
    const float* key   = (const float*)d_in[1];
    const float* value = (const float*)d_in[2];
    const float* Wq = (const float*)d_in[3];  const float* bq = (const float*)d_in[4];
    const float* Wk = (const float*)d_in[5];  const float* bk = (const float*)d_in[6];
    const float* Wv = (const float*)d_in[7];  const float* bv = (const float*)d_in[8];
    const float* Wo = (const float*)d_in[9];  const float* bo = (const float*)d_in[10];
    float* out = (float*)d_out;

    float *Wdq, *Xin, *Qb, *Kb, *Vb, *Vt, *Cx;
    cudaGetSymbolAddress((void**)&Wdq, g_Wdq);
    cudaGetSymbolAddress((void**)&Xin, g_Xin);
    cudaGetSymbolAddress((void**)&Qb,  g_Q);
    cudaGetSymbolAddress((void**)&Kb,  g_K);
    cudaGetSymbolAddress((void**)&Vb,  g_V);
    cudaGetSymbolAddress((void**)&Vt,  g_Vt);
    cudaGetSymbolAddress((void**)&Cx,  g_ctx);

    cudaFuncSetAttribute(gemm_mma<128, 256, 0>, cudaFuncAttributeMaxDynamicSharedMemorySize, SMEM_128);
    cudaFuncSetAttribute(gemm_mma<128, 256, 1>, cudaFuncAttributeMaxDynamicSharedMemorySize, SMEM_128);
    cudaFuncSetAttribute(gemm_mma<128, 256, 3>, cudaFuncAttributeMaxDynamicSharedMemorySize, SMEM_128);
    cudaFuncSetAttribute(k_flash, cudaFuncAttributeMaxDynamicSharedMemorySize, SMEM_FLASH);

    // 1) weight quant-dequant (+ tf32 RNA) and input tf32 RNA copies
    k_reset<<<1, 32>>>();
    k_absmax<<<dim3(256, 4), 256>>>(Wq, Wk, Wv, Wo);
    k_dequant<<<dim3(WELEMS / (256 * 4), 4), 256>>>(Wq, Wk, Wv, Wo);
    k_cvt_in<<<dim3(TOKENS * EMBED / (256 * 4), 3), 256>>>(query, key, value);

    // 2) Q/K projections (interleaved d), V projection (natural d)
    gemm_mma<128, 256, 3><<<dim3(EMBED / 128, TOKENS / 128, 1), 256, SMEM_128>>>(
        Xin + 0 * (size_t)TOKENS * EMBED, Wdq + 0 * (size_t)WELEMS, bq, Qb,
        EMBED, 0, 0, 1.0f, 0, 0);
    gemm_mma<128, 256, 3><<<dim3(EMBED / 128, TOKENS / 128, 1), 256, SMEM_128>>>(
        Xin + 1 * (size_t)TOKENS * EMBED, Wdq + 1 * (size_t)WELEMS, bk, Kb,
        EMBED, 0, 0, 1.0f, 0, 0);
    gemm_mma<128, 256, 1><<<dim3(EMBED / 128, TOKENS / 128, 1), 256, SMEM_128>>>(
        Xin + 2 * (size_t)TOKENS * EMBED, Wdq + 2 * (size_t)WELEMS, bv, Vb,
        EMBED, 0, 0, 1.0f, 0, 0);

    // 3) V transpose -> [B,H,D,Sperm]
    k_transpose_v<<<dim3(SEQ / 32, HDIM / 32, NBATCH * NHEADS), dim3(32, 8)>>>(Vb, Vt);

    // 4) fused attention (QK^T + online softmax + PV) -> ctx [B,S,E]
    k_flash<<<dim3(SEQ / BQ, 1, NBATCH * NHEADS), 256, SMEM_FLASH>>>(Qb, Kb, Vt, Cx);

    // 5) output projection -> d_out
    gemm_mma<128, 256, 0><<<dim3(EMBED / 128, TOKENS / 128, 1), 256, SMEM_128>>>(
        Cx, Wdq + 3 * (size_t)WELEMS, bo, out, EMBED, 0, 0, 1.0f, 0, EMBED);
}

// round 9
// speedup vs baseline: 1.1868x; 1.1868x over previous
#include <cuda_runtime.h>
#include <cstdint>

// ---------------------------------------------------------------------------
// Problem constants
// ---------------------------------------------------------------------------
#define EMBED   1024
#define NHEADS  16
#define HDIM    64
#define NBATCH  2
#define SEQ     2048
#define TOKENS  (NBATCH * SEQ)          // 4096
#define WELEMS  (EMBED * EMBED)         // 1048576
#define SCALE_ATTN 0.125f               // 1/sqrt(64)
#define SA 44                           // GEMM smem row stride (floats)

// Flash-attention tiling
#define BQ   128
#define BKV  64
#define NJ   (SEQ / BKV)                // 32
#define SQ8  68                         // flash smem row stride (64 + 4)

// ---------------------------------------------------------------------------
// Scratch (static __device__ globals; no runtime allocation allowed)
// ---------------------------------------------------------------------------
__device__ float g_Wdq[4 * WELEMS];                                  // tf32-rounded dequant weights
__device__ int   g_absmax[4];
__device__ float g_Xin[3 * (size_t)TOKENS * EMBED];                  // tf32-rounded inputs
__device__ float g_Q[(size_t)NBATCH * NHEADS * SEQ * HDIM];          // [B,H,S,D]
__device__ float g_K[(size_t)NBATCH * NHEADS * SEQ * HDIM];
__device__ float g_V[(size_t)NBATCH * NHEADS * SEQ * HDIM];
__device__ float g_Vt[(size_t)NBATCH * NHEADS * HDIM * SEQ];         // [B,H,D,S]
__device__ float g_ctx[(size_t)TOKENS * EMBED];                      // [B,S,E]

// ---------------------------------------------------------------------------
// Helpers (target-portable PTX only: mma.sync sm_80+, cp.async sm_80+)
// ---------------------------------------------------------------------------
__device__ __forceinline__ uint32_t smem_u32(const void* p) {
    uint32_t a;
    asm("{ .reg .u64 t; cvta.to.shared.u64 t, %1; cvt.u32.u64 %0, t; }" : "=r"(a) : "l"(p));
    return a;
}

__device__ __forceinline__ float rna_tf32(float x) {
    float r;
    asm("cvt.rna.tf32.f32 %0, %1;" : "=f"(r) : "f"(x));
    return r;
}

__device__ __forceinline__ void cp_async16(uint32_t saddr, const void* gaddr) {
    asm volatile("cp.async.cg.shared.global [%0], [%1], 16;"
                 :: "r"(saddr), "l"(gaddr) : "memory");
}

__device__ __forceinline__ void mma_tf32(float* d, const uint32_t* a, const uint32_t* b) {
    asm volatile(
        "mma.sync.aligned.m16n8k8.row.col.f32.tf32.tf32.f32 "
        "{%0,%1,%2,%3}, {%4,%5,%6,%7}, {%8,%9}, {%0,%1,%2,%3};"
        : "+f"(d[0]), "+f"(d[1]), "+f"(d[2]), "+f"(d[3])
        : "r"(a[0]), "r"(a[1]), "r"(a[2]), "r"(a[3]), "r"(b[0]), "r"(b[1]));
}

// ---------------------------------------------------------------------------
// Weight quantization (bit-faithful: s = max|W|/127, round-half-even, clip,
// dequantize), then RNA-round to tf32 so the MMA truncation is lossless.
// ---------------------------------------------------------------------------
__global__ void k_reset() { if (threadIdx.x < 4) g_absmax[threadIdx.x] = 0; }

__global__ void k_absmax(const float* __restrict__ w0, const float* __restrict__ w1,
                         const float* __restrict__ w2, const float* __restrict__ w3)
{
    const float* W = (blockIdx.y == 0) ? w0 : (blockIdx.y == 1) ? w1
                   : (blockIdx.y == 2) ? w2 : w3;
    float m = 0.0f;
    for (int i = blockIdx.x * blockDim.x + threadIdx.x; i < WELEMS;
         i += gridDim.x * blockDim.x)
        m = fmaxf(m, fabsf(W[i]));
    #pragma unroll
    for (int o = 16; o; o >>= 1) m = fmaxf(m, __shfl_xor_sync(0xffffffffu, m, o));
    if ((threadIdx.x & 31) == 0) atomicMax(&g_absmax[blockIdx.y], __float_as_int(m));
}

__global__ void k_dequant(const float* __restrict__ w0, const float* __restrict__ w1,
                          const float* __restrict__ w2, const float* __restrict__ w3)
{
    int sel = blockIdx.y;
    const float* W = (sel == 0) ? w0 : (sel == 1) ? w1 : (sel == 2) ? w2 : w3;
    float s = __int_as_float(g_absmax[sel]) / 127.0f;
    int i = (blockIdx.x * blockDim.x + threadIdx.x) * 4;
    float4 w = *(const float4*)&W[i];
    float4 r;
    r.x = rna_tf32(fminf(fmaxf(rintf(w.x / s), -128.0f), 127.0f) * s);
    r.y = rna_tf32(fminf(fmaxf(rintf(w.y / s), -128.0f), 127.0f) * s);
    r.z = rna_tf32(fminf(fmaxf(rintf(w.z / s), -128.0f), 127.0f) * s);
    r.w = rna_tf32(fminf(fmaxf(rintf(w.w / s), -128.0f), 127.0f) * s);
    *(float4*)&g_Wdq[(size_t)sel * WELEMS + i] = r;
}

__global__ void k_cvt_in(const float* __restrict__ q, const float* __restrict__ k,
                         const float* __restrict__ v)
{
    int sel = blockIdx.y;
    const float* s = (sel == 0) ? q : (sel == 1) ? k : v;
    float* d = g_Xin + (size_t)sel * TOKENS * EMBED;
    int i = (blockIdx.x * blockDim.x + threadIdx.x) * 4;
    float4 w = *(const float4*)&s[i];
    w.x = rna_tf32(w.x); w.y = rna_tf32(w.y);
    w.z = rna_tf32(w.z); w.w = rna_tf32(w.w);
    *(float4*)&d[i] = w;
}

// ---------------------------------------------------------------------------
// Tensor-core tf32 NT GEMM via mma.sync.m16n8k8 (R6 code, proven):
//   C[M, N] = alpha * A[M,K] * B[N,K]^T (+ bias)
// MODE 0: plain row-major out;  MODE 1: QKV scatter to [B,H,S,D], RNA-rounded
// ---------------------------------------------------------------------------
template <int BN, int NT, int MODE>
__global__ __launch_bounds__(NT, 2)
void gemm_mma(const float* __restrict__ A, const float* __restrict__ B,
              const float* __restrict__ bias, float* __restrict__ C,
              int K, long long aZ, long long bZ, float alpha, long long cZ, int ldc)
{
    extern __shared__ float smem[];
    constexpr int STF = (128 + BN) * SA;

    const int tid  = threadIdx.x;
    const int wid  = tid >> 5, lane = tid & 31;
    const int wm   = wid & 1, wn = wid >> 1;
    const int qid  = lane >> 2, tig = lane & 3;

    const float* gA = A + (long long)blockIdx.z * aZ + (size_t)(blockIdx.y * 128) * K;
    const float* gB = B + (long long)blockIdx.z * bZ + (size_t)(blockIdx.x * BN) * K;

    float acc[4][4][4] = {};

    auto loadStage = [&](int s, int k0) {
        float* sAp = smem + s * STF;
        float* sBp = sAp + 128 * SA;
        const int r0 = tid >> 3, c = (tid & 7) * 4;
        #pragma unroll
        for (int it = 0; it < 128 * 8 / NT; ++it) {
            const int r = r0 + it * (NT / 8);
            cp_async16(smem_u32(sAp + r * SA + c), gA + (size_t)r * K + k0 + c);
        }
        #pragma unroll
        for (int it = 0; it < BN * 8 / NT; ++it) {
            const int r = r0 + it * (NT / 8);
            cp_async16(smem_u32(sBp + r * SA + c), gB + (size_t)r * K + k0 + c);
        }
        asm volatile("cp.async.commit_group;" ::: "memory");
    };

    const int ns = K / 32;
    loadStage(0, 0);
    for (int i = 0; i < ns; ++i) {
        if (i + 1 < ns) {
            loadStage((i + 1) & 1, (i + 1) * 32);
            asm volatile("cp.async.wait_group 1;" ::: "memory");
        } else {
            asm volatile("cp.async.wait_group 0;" ::: "memory");
        }
        __syncthreads();

        const float* sAp = smem + (i & 1) * STF;
        const float* sBp = sAp + 128 * SA;
        #pragma unroll
        for (int ks = 0; ks < 4; ++ks) {
            const int k = ks * 8 + tig;
            uint32_t af[4][4], bf[4][2];
            #pragma unroll
            for (int mt = 0; mt < 4; ++mt) {
                const float* ap = sAp + (wm * 64 + mt * 16 + qid) * SA + k;
                af[mt][0] = __float_as_uint(ap[0]);
                af[mt][1] = __float_as_uint(ap[8 * SA]);
                af[mt][2] = __float_as_uint(ap[4]);
                af[mt][3] = __float_as_uint(ap[8 * SA + 4]);
            }
            #pragma unroll
            for (int nt = 0; nt < 4; ++nt) {
                const float* bp = sBp + (wn * 32 + nt * 8 + qid) * SA + k;
                bf[nt][0] = __float_as_uint(bp[0]);
                bf[nt][1] = __float_as_uint(bp[4]);
            }
            #pragma unroll
            for (int mt = 0; mt < 4; ++mt)
                #pragma unroll
                for (int nt = 0; nt < 4; ++nt)
                    mma_tf32(acc[mt][nt], af[mt], bf[nt]);
        }
        __syncthreads();
    }

    const int z = blockIdx.z;
    #pragma unroll
    for (int mt = 0; mt < 4; ++mt) {
        const int m = blockIdx.y * 128 + wm * 64 + mt * 16 + qid;
        #pragma unroll
        for (int nt = 0; nt < 4; ++nt) {
            const int n = blockIdx.x * BN + wn * 32 + nt * 8 + tig * 2;
            float c0 = acc[mt][nt][0], c1 = acc[mt][nt][1];
            float c2 = acc[mt][nt][2], c3 = acc[mt][nt][3];

            if (MODE == 0) {
                c0 *= alpha; c1 *= alpha; c2 *= alpha; c3 *= alpha;
                if (bias) {
                    const float b0 = bias[n], b1 = bias[n + 1];
                    c0 += b0; c1 += b1; c2 += b0; c3 += b1;
                }
                float* p0 = C + (long long)z * cZ + (size_t)m * ldc + n;
                float* p1 = C + (long long)z * cZ + (size_t)(m + 8) * ldc + n;
                *(float2*)p0 = make_float2(c0, c1);
                *(float2*)p1 = make_float2(c2, c3);
            } else {
                const int b = m >> 11, s2 = m & (SEQ - 1);
                const int h = n >> 6, d = n & (HDIM - 1);
                const float b0 = bias[n], b1 = bias[n + 1];
                c0 = rna_tf32(c0 + b0); c1 = rna_tf32(c1 + b1);
                c2 = rna_tf32(c2 + b0); c3 = rna_tf32(c3 + b1);
                const size_t base = ((size_t)b * NHEADS + h) * SEQ;
                *(float2*)&C[(base + s2) * HDIM + d]     = make_float2(c0, c1);
                *(float2*)&C[(base + s2 + 8) * HDIM + d] = make_float2(c2, c3);
            }
        }
    }
}

// ---------------------------------------------------------------------------
// V transpose: [BH,S,64] -> [BH,64,S]  natural (R6)
// ---------------------------------------------------------------------------
__global__ void k_transpose_v(const float* __restrict__ V, float* __restrict__ Vt)
{
    __shared__ float t[32][33];
    const int bh = blockIdx.z;
    const int s0 = blockIdx.x * 32, d0 = blockIdx.y * 32;
    const float* src = V + (size_t)bh * SEQ * HDIM;
    float* dst = Vt + (size_t)bh * HDIM * SEQ;
    const int x = threadIdx.x, y = threadIdx.y;    // 32 x 8
    #pragma unroll
    for (int i = 0; i < 32; i += 8)
        t[y + i][x] = src[(size_t)(s0 + y + i) * HDIM + d0 + x];
    __syncthreads();
    #pragma unroll
    for (int i = 0; i < 32; i += 8)
        dst[(size_t)(d0 + y + i) * SEQ + s0 + x] = t[x][y + i];
}

// ---------------------------------------------------------------------------
// Fused flash attention, v4 = R6 + key-permuted K tile rows.
// K tile physical row p holds logical key (p>>1 in-octet) + ((p&1)<<2), so
// the S C-frag slots {2t, 2t+1} hold logical keys {t, t+4}: the P·V A-frag
// is a pure register renaming of the softmaxed C-frag (no shuffles, no smem).
// The V^T B-operand in NATURAL layout already supplies keys {t, t+4} at
// scalar offsets k and k+4 (exactly the R6 conflict-free access pattern).
// Softmax is column-permutation invariant. Everything else identical to R6.
// ---------------------------------------------------------------------------
__global__ __launch_bounds__(256, 2)
void k_flash(const float* __restrict__ Qg, const float* __restrict__ Kg,
             const float* __restrict__ Vtg, float* __restrict__ ctx)
{
    extern __shared__ float sm[];
    float* Qs = sm;                       // 128 x SQ8
    float* Ks = Qs + BQ * SQ8;            // 2 x 64 x SQ8   [key_perm][d]
    float* Vs = Ks + 2 * BKV * SQ8;       // 2 x 64 x SQ8   [d][key] natural

    const int tid = threadIdx.x;
    const int wid = tid >> 5, lane = tid & 31;
    const int qid = lane >> 2, tig = lane & 3;
    const int bh = blockIdx.z;
    const int b = bh >> 4, h = bh & 15;

    const float* gQ = Qg + ((size_t)bh * SEQ + blockIdx.x * BQ) * HDIM;
    const float* gK = Kg + (size_t)bh * SEQ * HDIM;
    const float* gV = Vtg + (size_t)bh * HDIM * SEQ;

    // Q tile load (own group)
    #pragma unroll
    for (int it = 0; it < 8; ++it) {
        int lin = tid + it * 256;              // 0..2047 -> 128 rows x 16 float4
        int r = lin >> 4, c = (lin & 15) * 4;
        cp_async16(smem_u32(Qs + r * SQ8 + c), gQ + (size_t)r * HDIM + c);
    }
    asm volatile("cp.async.commit_group;" ::: "memory");

    auto loadKV = [&](int j, int buf) {
        float* kd = Ks + buf * BKV * SQ8;
        float* vd = Vs + buf * HDIM * SQ8;
        #pragma unroll
        for (int it = 0; it < 4; ++it) {
            int lin = tid + it * 256;          // 0..1023 -> 64 rows x 16 float4
            int r = lin >> 4, c = (lin & 15) * 4;
            // physical row r holds logical key (in-octet) ((r&7)>>1) + ((r&1)<<2)
            int rsrc = (r & ~7) | (((r & 7) >> 1) | ((r & 1) << 2));
            cp_async16(smem_u32(kd + r * SQ8 + c), gK + (size_t)(j * BKV + rsrc) * HDIM + c);
            cp_async16(smem_u32(vd + r * SQ8 + c), gV + (size_t)r * SEQ + j * BKV + c);
        }
        asm volatile("cp.async.commit_group;" ::: "memory");
    };

    loadKV(0, 0);

    float mrow0 = -1e30f, mrow1 = -1e30f;
    float lrow0 = 0.0f, lrow1 = 0.0f;
    float o[8][4] = {};
    const int rq = wid * 16 + qid;             // warp-private row (and +8)

    for (int j = 0; j < NJ; ++j) {
        if (j + 1 < NJ) {
            loadKV(j + 1, (j + 1) & 1);
            asm volatile("cp.async.wait_group 1;" ::: "memory");
        } else {
            asm volatile("cp.async.wait_group 0;" ::: "memory");
        }
        __syncthreads();                       // tile j visible to all warps

        // ---- S = Q K^T  (16 rows x 64 keys per warp; R6 scalar loads) ----
        float s[8][4] = {};
        const float* kb = Ks + (j & 1) * BKV * SQ8;
        #pragma unroll
        for (int ks = 0; ks < 8; ++ks) {
            const int k = ks * 8 + tig;
            uint32_t af[4];
            const float* ap = Qs + rq * SQ8 + k;
            af[0] = __float_as_uint(ap[0]);
            af[1] = __float_as_uint(ap[8 * SQ8]);
            af[2] = __float_as_uint(ap[4]);
            af[3] = __float_as_uint(ap[8 * SQ8 + 4]);
            #pragma unroll
            for (int nt = 0; nt < 8; ++nt) {
                const float* bp = kb + (nt * 8 + qid) * SQ8 + k;
                uint32_t bf[2] = {__float_as_uint(bp[0]), __float_as_uint(bp[4])};
                mma_tf32(s[nt], af, bf);
            }
        }

        // ---- online softmax (rows rq and rq+8), P kept in s[][] ----
        // (columns are a key permutation; row reductions are order-invariant)
        float mx0 = -1e30f, mx1 = -1e30f;
        #pragma unroll
        for (int nt = 0; nt < 8; ++nt) {
            s[nt][0] *= SCALE_ATTN; s[nt][1] *= SCALE_ATTN;
            s[nt][2] *= SCALE_ATTN; s[nt][3] *= SCALE_ATTN;
            mx0 = fmaxf(mx0, fmaxf(s[nt][0], s[nt][1]));
            mx1 = fmaxf(mx1, fmaxf(s[nt][2], s[nt][3]));
        }
        mx0 = fmaxf(mx0, __shfl_xor_sync(0xffffffffu, mx0, 1));
        mx0 = fmaxf(mx0, __shfl_xor_sync(0xffffffffu, mx0, 2));
        mx1 = fmaxf(mx1, __shfl_xor_sync(0xffffffffu, mx1, 1));
        mx1 = fmaxf(mx1, __shfl_xor_sync(0xffffffffu, mx1, 2));
        const float mn0 = fmaxf(mrow0, mx0), mn1 = fmaxf(mrow1, mx1);
        const float a0 = __expf(mrow0 - mn0), a1 = __expf(mrow1 - mn1);
        mrow0 = mn0; mrow1 = mn1;

        float sum0 = 0.0f, sum1 = 0.0f;
        #pragma unroll
        for (int nt = 0; nt < 8; ++nt) {
            const float p0 = __expf(s[nt][0] - mn0), p1 = __expf(s[nt][1] - mn0);
            const float p2 = __expf(s[nt][2] - mn1), p3 = __expf(s[nt][3] - mn1);
            sum0 += p0 + p1; sum1 += p2 + p3;
            s[nt][0] = rna_tf32(p0); s[nt][1] = rna_tf32(p1);
            s[nt][2] = rna_tf32(p2); s[nt][3] = rna_tf32(p3);
        }
        sum0 += __shfl_xor_sync(0xffffffffu, sum0, 1);
        sum0 += __shfl_xor_sync(0xffffffffu, sum0, 2);
        sum1 += __shfl_xor_sync(0xffffffffu, sum1, 1);
        sum1 += __shfl_xor_sync(0xffffffffu, sum1, 2);
        lrow0 = lrow0 * a0 + sum0;
        lrow1 = lrow1 * a1 + sum1;
        #pragma unroll
        for (int nt = 0; nt < 8; ++nt) {
            o[nt][0] *= a0; o[nt][1] *= a0;
            o[nt][2] *= a1; o[nt][3] *= a1;
        }

        // ---- O += P V : A-frag = renamed C-frag (key perm), B natural ----
        const float* vb = Vs + (j & 1) * HDIM * SQ8;
        #pragma unroll
        for (int kc = 0; kc < 8; ++kc) {
            uint32_t af[4];
            af[0] = __float_as_uint(s[kc][0]);   // (row rq,   key kc*8+tig)
            af[1] = __float_as_uint(s[kc][2]);   // (row rq+8, key kc*8+tig)
            af[2] = __float_as_uint(s[kc][1]);   // (row rq,   key kc*8+tig+4)
            af[3] = __float_as_uint(s[kc][3]);   // (row rq+8, key kc*8+tig+4)
            const int k = kc * 8 + tig;
            #pragma unroll
            for (int nt = 0; nt < 8; ++nt) {
                const float* bp = vb + (nt * 8 + qid) * SQ8 + k;
                uint32_t bf[2] = {__float_as_uint(bp[0]), __float_as_uint(bp[4])};
                mma_tf32(o[nt], af, bf);
            }
        }
        __syncthreads();                       // all reads done before next prefetch lands
    }

    // ---- epilogue: O /= l, RNA-round (feeds out-proj tf32 mma), write ctx ----
    const float inv0 = 1.0f / lrow0, inv1 = 1.0f / lrow1;
    const int q0 = blockIdx.x * BQ + rq;
    float* dst0 = ctx + ((size_t)b * SEQ + q0) * EMBED + h * HDIM;
    float* dst1 = ctx + ((size_t)b * SEQ + q0 + 8) * EMBED + h * HDIM;
    #pragma unroll
    for (int nt = 0; nt < 8; ++nt) {
        const int d = nt * 8 + tig * 2;
        *(float2*)&dst0[d] = make_float2(rna_tf32(o[nt][0] * inv0),
                                         rna_tf32(o[nt][1] * inv0));
        *(float2*)&dst1[d] = make_float2(rna_tf32(o[nt][2] * inv1),
                                         rna_tf32(o[nt][3] * inv1));
    }
}

// ---------------------------------------------------------------------------
// Launch
// ---------------------------------------------------------------------------
#define SMEM_128   ((128 + 128) * SA * 4 * 2)              // 90112 B
#define SMEM_FLASH ((BQ + 2 * BKV + 2 * HDIM) * SQ8 * 4)   // 104448 B -> 2 CTAs/SM

extern "C" void kernel_launch(void* const* d_in, const int* in_sizes, int n_in,
                              void* d_out, int out_size)
{
    (void)in_sizes; (void)n_in; (void)out_size;
    const float* query = (const float*)d_in[0];
    const float* key   = (const float*)d_in[1];
    const float* value = (const float*)d_in[2];
    const float* Wq = (const float*)d_in[3];  const float* bq = (const float*)d_in[4];
    const float* Wk = (const float*)d_in[5];  const float* bk = (const float*)d_in[6];
    const float* Wv = (const float*)d_in[7];  const float* bv = (const float*)d_in[8];
    const float* Wo = (const float*)d_in[9];  const float* bo = (const float*)d_in[10];
    float* out = (float*)d_out;

    float *Wdq, *Xin, *Qb, *Kb, *Vb, *Vt, *Cx;
    cudaGetSymbolAddress((void**)&Wdq, g_Wdq);
    cudaGetSymbolAddress((void**)&Xin, g_Xin);
    cudaGetSymbolAddress((void**)&Qb,  g_Q);
    cudaGetSymbolAddress((void**)&Kb,  g_K);
    cudaGetSymbolAddress((void**)&Vb,  g_V);
    cudaGetSymbolAddress((void**)&Vt,  g_Vt);
    cudaGetSymbolAddress((void**)&Cx,  g_ctx);

    cudaFuncSetAttribute(gemm_mma<128, 256, 0>, cudaFuncAttributeMaxDynamicSharedMemorySize, SMEM_128);
    cudaFuncSetAttribute(gemm_mma<128, 256, 1>, cudaFuncAttributeMaxDynamicSharedMemorySize, SMEM_128);
    cudaFuncSetAttribute(k_flash, cudaFuncAttributeMaxDynamicSharedMemorySize, SMEM_FLASH);

    // 1) weight quant-dequant (+ tf32 RNA) and input tf32 RNA copies
    k_reset<<<1, 32>>>();
    k_absmax<<<dim3(256, 4), 256>>>(Wq, Wk, Wv, Wo);
    k_dequant<<<dim3(WELEMS / (256 * 4), 4), 256>>>(Wq, Wk, Wv, Wo);
    k_cvt_in<<<dim3(TOKENS * EMBED / (256 * 4), 3), 256>>>(query, key, value);

    // 2) Q/K/V projections -> [B,H,S,D] (tf32-rounded outputs)
    gemm_mma<128, 256, 1><<<dim3(EMBED / 128, TOKENS / 128, 1), 256, SMEM_128>>>(
        Xin + 0 * (size_t)TOKENS * EMBED, Wdq + 0 * (size_t)WELEMS, bq, Qb,
        EMBED, 0, 0, 1.0f, 0, 0);
    gemm_mma<128, 256, 1><<<dim3(EMBED / 128, TOKENS / 128, 1), 256, SMEM_128>>>(
        Xin + 1 * (size_t)TOKENS * EMBED, Wdq + 1 * (size_t)WELEMS, bk, Kb,
        EMBED, 0, 0, 1.0f, 0, 0);
    gemm_mma<128, 256, 1><<<dim3(EMBED / 128, TOKENS / 128, 1), 256, SMEM_128>>>(
        Xin + 2 * (size_t)TOKENS * EMBED, Wdq + 2 * (size_t)WELEMS, bv, Vb,
        EMBED, 0, 0, 1.0f, 0, 0);

    // 3) V transpose -> [B,H,D,S] natural
    k_transpose_v<<<dim3(SEQ / 32, HDIM / 32, NBATCH * NHEADS), dim3(32, 8)>>>(Vb, Vt);

    // 4) fused attention (QK^T + online softmax + PV) -> ctx [B,S,E]
    k_flash<<<dim3(SEQ / BQ, 1, NBATCH * NHEADS), 256, SMEM_FLASH>>>(Qb, Kb, Vt, Cx);

    // 5) output projection -> d_out
    gemm_mma<128, 256, 0><<<dim3(EMBED / 128, TOKENS / 128, 1), 256, SMEM_128>>>(
        Cx, Wdq + 3 * (size_t)WELEMS, bo, out, EMBED, 0, 0, 1.0f, 0, EMBED);
}

// round 10
// speedup vs baseline: 1.2259x; 1.0329x over previous
#include <cuda_runtime.h>
#include <cstdint>

// ---------------------------------------------------------------------------
// Problem constants
// ---------------------------------------------------------------------------
#define EMBED   1024
#define NHEADS  16
#define HDIM    64
#define NBATCH  2
#define SEQ     2048
#define TOKENS  (NBATCH * SEQ)          // 4096
#define WELEMS  (EMBED * EMBED)         // 1048576
#define SCALE_ATTN 0.125f               // 1/sqrt(64)
#define SA 44                           // GEMM smem row stride (floats)

// Flash-attention tiling
#define BQ   128
#define BKV  64
#define NJ   (SEQ / BKV)                // 32
#define SQ8  68                         // flash smem row stride (64 + 4)

// ---------------------------------------------------------------------------
// Scratch (static __device__ globals; no runtime allocation allowed)
// ---------------------------------------------------------------------------
__device__ float g_Wdq[4 * WELEMS];                                  // tf32-rounded dequant weights
__device__ int   g_absmax[4];
__device__ float g_QK[2 * (size_t)NBATCH * NHEADS * SEQ * HDIM];     // Q then K, [B,H,S,D]
__device__ float g_Vt[(size_t)NBATCH * NHEADS * HDIM * SEQ];         // [B,H,D,S]
__device__ float g_ctx[(size_t)TOKENS * EMBED];                      // [B,S,E]

// ---------------------------------------------------------------------------
// Helpers (target-portable PTX only: mma.sync sm_80+, cp.async sm_80+)
// ---------------------------------------------------------------------------
__device__ __forceinline__ uint32_t smem_u32(const void* p) {
    uint32_t a;
    asm("{ .reg .u64 t; cvta.to.shared.u64 t, %1; cvt.u32.u64 %0, t; }" : "=r"(a) : "l"(p));
    return a;
}

__device__ __forceinline__ float rna_tf32(float x) {
    float r;
    asm("cvt.rna.tf32.f32 %0, %1;" : "=f"(r) : "f"(x));
    return r;
}

__device__ __forceinline__ uint32_t rna_tf32_u(float x) {
    float r;
    asm("cvt.rna.tf32.f32 %0, %1;" : "=f"(r) : "f"(x));
    return __float_as_uint(r);
}

__device__ __forceinline__ void cp_async16(uint32_t saddr, const void* gaddr) {
    asm volatile("cp.async.cg.shared.global [%0], [%1], 16;"
                 :: "r"(saddr), "l"(gaddr) : "memory");
}

__device__ __forceinline__ void mma_tf32(float* d, const uint32_t* a, const uint32_t* b) {
    asm volatile(
        "mma.sync.aligned.m16n8k8.row.col.f32.tf32.tf32.f32 "
        "{%0,%1,%2,%3}, {%4,%5,%6,%7}, {%8,%9}, {%0,%1,%2,%3};"
        : "+f"(d[0]), "+f"(d[1]), "+f"(d[2]), "+f"(d[3])
        : "r"(a[0]), "r"(a[1]), "r"(a[2]), "r"(a[3]), "r"(b[0]), "r"(b[1]));
}

// ---------------------------------------------------------------------------
// Weight quantization (bit-faithful: s = max|W|/127, round-half-even, clip,
// dequantize), then RNA-round to tf32 so the MMA truncation is lossless.
// ---------------------------------------------------------------------------
__global__ void k_reset() { if (threadIdx.x < 4) g_absmax[threadIdx.x] = 0; }

__global__ void k_absmax(const float* __restrict__ w0, const float* __restrict__ w1,
                         const float* __restrict__ w2, const float* __restrict__ w3)
{
    const float* W = (blockIdx.y == 0) ? w0 : (blockIdx.y == 1) ? w1
                   : (blockIdx.y == 2) ? w2 : w3;
    float m = 0.0f;
    for (int i = blockIdx.x * blockDim.x + threadIdx.x; i < WELEMS;
         i += gridDim.x * blockDim.x)
        m = fmaxf(m, fabsf(W[i]));
    #pragma unroll
    for (int o = 16; o; o >>= 1) m = fmaxf(m, __shfl_xor_sync(0xffffffffu, m, o));
    if ((threadIdx.x & 31) == 0) atomicMax(&g_absmax[blockIdx.y], __float_as_int(m));
}

__global__ void k_dequant(const float* __restrict__ w0, const float* __restrict__ w1,
                          const float* __restrict__ w2, const float* __restrict__ w3)
{
    int sel = blockIdx.y;
    const float* W = (sel == 0) ? w0 : (sel == 1) ? w1 : (sel == 2) ? w2 : w3;
    float s = __int_as_float(g_absmax[sel]) / 127.0f;
    int i = (blockIdx.x * blockDim.x + threadIdx.x) * 4;
    float4 w = *(const float4*)&W[i];
    float4 r;
    r.x = rna_tf32(fminf(fmaxf(rintf(w.x / s), -128.0f), 127.0f) * s);
    r.y = rna_tf32(fminf(fmaxf(rintf(w.y / s), -128.0f), 127.0f) * s);
    r.z = rna_tf32(fminf(fmaxf(rintf(w.z / s), -128.0f), 127.0f) * s);
    r.w = rna_tf32(fminf(fmaxf(rintf(w.w / s), -128.0f), 127.0f) * s);
    *(float4*)&g_Wdq[(size_t)sel * WELEMS + i] = r;
}

// ---------------------------------------------------------------------------
// Fused Q/K/V projection GEMM (one launch, grid z in {0,1,2}):
//   P = rna(X_z) * Wdq_z^T + b_z      (A fragments RNA-rounded post-LDS —
//                                      bit-identical to pre-rounding in gmem)
//   z in {0,1}: write [B,H,S,D] into g_QK + z*offset   (Q, K)
//   z == 2   : write [B,H,D,S] into g_Vt (fused transpose; for fixed tig the
//              8 qid lanes fill one 32B sector of a d-row -> fully packed)
// CTA tile 128x128, BK=32 double-buffered, 256 threads, warp tile 64x32.
// ---------------------------------------------------------------------------
__global__ __launch_bounds__(256, 2)
void gemm_proj(const float* __restrict__ A0, const float* __restrict__ A1,
               const float* __restrict__ A2,
               const float* __restrict__ b0, const float* __restrict__ b1,
               const float* __restrict__ b2)
{
    extern __shared__ float smem[];
    constexpr int STF = 256 * SA;

    const int tid  = threadIdx.x;
    const int wid  = tid >> 5, lane = tid & 31;
    const int wm   = wid & 1, wn = wid >> 1;
    const int qid  = lane >> 2, tig = lane & 3;
    const int z    = blockIdx.z;

    const float* A = (z == 0) ? A0 : (z == 1) ? A1 : A2;
    const float* bias = (z == 0) ? b0 : (z == 1) ? b1 : b2;
    const float* gA = A + (size_t)(blockIdx.y * 128) * EMBED;
    const float* gB = g_Wdq + (size_t)z * WELEMS + (size_t)(blockIdx.x * 128) * EMBED;

    float acc[4][4][4] = {};

    auto loadStage = [&](int s, int k0) {
        float* sAp = smem + s * STF;
        float* sBp = sAp + 128 * SA;
        const int r0 = tid >> 3, c = (tid & 7) * 4;
        #pragma unroll
        for (int it = 0; it < 4; ++it) {
            const int r = r0 + it * 32;
            cp_async16(smem_u32(sAp + r * SA + c), gA + (size_t)r * EMBED + k0 + c);
        }
        #pragma unroll
        for (int it = 0; it < 4; ++it) {
            const int r = r0 + it * 32;
            cp_async16(smem_u32(sBp + r * SA + c), gB + (size_t)r * EMBED + k0 + c);
        }
        asm volatile("cp.async.commit_group;" ::: "memory");
    };

    const int ns = EMBED / 32;
    loadStage(0, 0);
    for (int i = 0; i < ns; ++i) {
        if (i + 1 < ns) {
            loadStage((i + 1) & 1, (i + 1) * 32);
            asm volatile("cp.async.wait_group 1;" ::: "memory");
        } else {
            asm volatile("cp.async.wait_group 0;" ::: "memory");
        }
        __syncthreads();

        const float* sAp = smem + (i & 1) * STF;
        const float* sBp = sAp + 128 * SA;
        #pragma unroll
        for (int ks = 0; ks < 4; ++ks) {
            const int k = ks * 8 + tig;
            uint32_t af[4][4], bf[4][2];
            #pragma unroll
            for (int mt = 0; mt < 4; ++mt) {
                const float* ap = sAp + (wm * 64 + mt * 16 + qid) * SA + k;
                af[mt][0] = rna_tf32_u(ap[0]);           // raw input -> tf32 RNA
                af[mt][1] = rna_tf32_u(ap[8 * SA]);
                af[mt][2] = rna_tf32_u(ap[4]);
                af[mt][3] = rna_tf32_u(ap[8 * SA + 4]);
            }
            #pragma unroll
            for (int nt = 0; nt < 4; ++nt) {
                const float* bp = sBp + (wn * 32 + nt * 8 + qid) * SA + k;
                bf[nt][0] = __float_as_uint(bp[0]);      // weights pre-rounded
                bf[nt][1] = __float_as_uint(bp[4]);
            }
            #pragma unroll
            for (int mt = 0; mt < 4; ++mt)
                #pragma unroll
                for (int nt = 0; nt < 4; ++nt)
                    mma_tf32(acc[mt][nt], af[mt], bf[nt]);
        }
        __syncthreads();
    }

    #pragma unroll
    for (int mt = 0; mt < 4; ++mt) {
        const int m = blockIdx.y * 128 + wm * 64 + mt * 16 + qid;
        const int b = m >> 11, s2 = m & (SEQ - 1);
        #pragma unroll
        for (int nt = 0; nt < 4; ++nt) {
            const int n = blockIdx.x * 128 + wn * 32 + nt * 8 + tig * 2;
            const int h = n >> 6, d = n & (HDIM - 1);
            const float bb0 = bias[n], bb1 = bias[n + 1];
            const float c0 = rna_tf32(acc[mt][nt][0] + bb0);
            const float c1 = rna_tf32(acc[mt][nt][1] + bb1);
            const float c2 = rna_tf32(acc[mt][nt][2] + bb0);
            const float c3 = rna_tf32(acc[mt][nt][3] + bb1);
            if (z < 2) {
                float* C = g_QK + (size_t)z * ((size_t)NBATCH * NHEADS * SEQ * HDIM);
                const size_t base = ((size_t)b * NHEADS + h) * SEQ;
                *(float2*)&C[(base + s2) * HDIM + d]     = make_float2(c0, c1);
                *(float2*)&C[(base + s2 + 8) * HDIM + d] = make_float2(c2, c3);
            } else {
                // V -> transposed [B,H,D,S]
                const size_t base = ((size_t)b * NHEADS + h) * HDIM;
                g_Vt[(base + d)     * SEQ + s2]     = c0;
                g_Vt[(base + d + 1) * SEQ + s2]     = c1;
                g_Vt[(base + d)     * SEQ + s2 + 8] = c2;
                g_Vt[(base + d + 1) * SEQ + s2 + 8] = c3;
            }
        }
    }
}

// ---------------------------------------------------------------------------
// Output projection GEMM (MODE0 of the proven R6 kernel, A already rounded)
// ---------------------------------------------------------------------------
__global__ __launch_bounds__(256, 2)
void gemm_out(const float* __restrict__ A, const float* __restrict__ B,
              const float* __restrict__ bias, float* __restrict__ C)
{
    extern __shared__ float smem[];
    constexpr int STF = 256 * SA;

    const int tid  = threadIdx.x;
    const int wid  = tid >> 5, lane = tid & 31;
    const int wm   = wid & 1, wn = wid >> 1;
    const int qid  = lane >> 2, tig = lane & 3;

    const float* gA = A + (size_t)(blockIdx.y * 128) * EMBED;
    const float* gB = B + (size_t)(blockIdx.x * 128) * EMBED;

    float acc[4][4][4] = {};

    auto loadStage = [&](int s, int k0) {
        float* sAp = smem + s * STF;
        float* sBp = sAp + 128 * SA;
        const int r0 = tid >> 3, c = (tid & 7) * 4;
        #pragma unroll
        for (int it = 0; it < 4; ++it) {
            const int r = r0 + it * 32;
            cp_async16(smem_u32(sAp + r * SA + c), gA + (size_t)r * EMBED + k0 + c);
        }
        #pragma unroll
        for (int it = 0; it < 4; ++it) {
            const int r = r0 + it * 32;
            cp_async16(smem_u32(sBp + r * SA + c), gB + (size_t)r * EMBED + k0 + c);
        }
        asm volatile("cp.async.commit_group;" ::: "memory");
    };

    const int ns = EMBED / 32;
    loadStage(0, 0);
    for (int i = 0; i < ns; ++i) {
        if (i + 1 < ns) {
            loadStage((i + 1) & 1, (i + 1) * 32);
            asm volatile("cp.async.wait_group 1;" ::: "memory");
        } else {
            asm volatile("cp.async.wait_group 0;" ::: "memory");
        }
        __syncthreads();

        const float* sAp = smem + (i & 1) * STF;
        const float* sBp = sAp + 128 * SA;
        #pragma unroll
        for (int ks = 0; ks < 4; ++ks) {
            const int k = ks * 8 + tig;
            uint32_t af[4][4], bf[4][2];
            #pragma unroll
            for (int mt = 0; mt < 4; ++mt) {
                const float* ap = sAp + (wm * 64 + mt * 16 + qid) * SA + k;
                af[mt][0] = __float_as_uint(ap[0]);
                af[mt][1] = __float_as_uint(ap[8 * SA]);
                af[mt][2] = __float_as_uint(ap[4]);
                af[mt][3] = __float_as_uint(ap[8 * SA + 4]);
            }
            #pragma unroll
            for (int nt = 0; nt < 4; ++nt) {
                const float* bp = sBp + (wn * 32 + nt * 8 + qid) * SA + k;
                bf[nt][0] = __float_as_uint(bp[0]);
                bf[nt][1] = __float_as_uint(bp[4]);
            }
            #pragma unroll
            for (int mt = 0; mt < 4; ++mt)
                #pragma unroll
                for (int nt = 0; nt < 4; ++nt)
                    mma_tf32(acc[mt][nt], af[mt], bf[nt]);
        }
        __syncthreads();
    }

    #pragma unroll
    for (int mt = 0; mt < 4; ++mt) {
        const int m = blockIdx.y * 128 + wm * 64 + mt * 16 + qid;
        #pragma unroll
        for (int nt = 0; nt < 4; ++nt) {
            const int n = blockIdx.x * 128 + wn * 32 + nt * 8 + tig * 2;
            const float b0 = bias[n], b1 = bias[n + 1];
            *(float2*)&C[(size_t)m * EMBED + n] =
                make_float2(acc[mt][nt][0] + b0, acc[mt][nt][1] + b1);
            *(float2*)&C[(size_t)(m + 8) * EMBED + n] =
                make_float2(acc[mt][nt][2] + b0, acc[mt][nt][3] + b1);
        }
    }
}

// ---------------------------------------------------------------------------
// Fused flash attention (R9 winner, unchanged): key-permuted K tile rows so
// the P·V A-frag is a register renaming of the softmaxed S C-frag.
// ---------------------------------------------------------------------------
__global__ __launch_bounds__(256, 2)
void k_flash(const float* __restrict__ Qg, const float* __restrict__ Kg,
             const float* __restrict__ Vtg, float* __restrict__ ctx)
{
    extern __shared__ float sm[];
    float* Qs = sm;                       // 128 x SQ8
    float* Ks = Qs + BQ * SQ8;            // 2 x 64 x SQ8   [key_perm][d]
    float* Vs = Ks + 2 * BKV * SQ8;       // 2 x 64 x SQ8   [d][key] natural

    const int tid = threadIdx.x;
    const int wid = tid >> 5, lane = tid & 31;
    const int qid = lane >> 2, tig = lane & 3;
    const int bh = blockIdx.z;
    const int b = bh >> 4, h = bh & 15;

    const float* gQ = Qg + ((size_t)bh * SEQ + blockIdx.x * BQ) * HDIM;
    const float* gK = Kg + (size_t)bh * SEQ * HDIM;
    const float* gV = Vtg + (size_t)bh * HDIM * SEQ;

    #pragma unroll
    for (int it = 0; it < 8; ++it) {
        int lin = tid + it * 256;
        int r = lin >> 4, c = (lin & 15) * 4;
        cp_async16(smem_u32(Qs + r * SQ8 + c), gQ + (size_t)r * HDIM + c);
    }
    asm volatile("cp.async.commit_group;" ::: "memory");

    auto loadKV = [&](int j, int buf) {
        float* kd = Ks + buf * BKV * SQ8;
        float* vd = Vs + buf * HDIM * SQ8;
        #pragma unroll
        for (int it = 0; it < 4; ++it) {
            int lin = tid + it * 256;
            int r = lin >> 4, c = (lin & 15) * 4;
            int rsrc = (r & ~7) | (((r & 7) >> 1) | ((r & 1) << 2));
            cp_async16(smem_u32(kd + r * SQ8 + c), gK + (size_t)(j * BKV + rsrc) * HDIM + c);
            cp_async16(smem_u32(vd + r * SQ8 + c), gV + (size_t)r * SEQ + j * BKV + c);
        }
        asm volatile("cp.async.commit_group;" ::: "memory");
    };

    loadKV(0, 0);

    float mrow0 = -1e30f, mrow1 = -1e30f;
    float lrow0 = 0.0f, lrow1 = 0.0f;
    float o[8][4] = {};
    const int rq = wid * 16 + qid;

    for (int j = 0; j < NJ; ++j) {
        if (j + 1 < NJ) {
            loadKV(j + 1, (j + 1) & 1);
            asm volatile("cp.async.wait_group 1;" ::: "memory");
        } else {
            asm volatile("cp.async.wait_group 0;" ::: "memory");
        }
        __syncthreads();

        float s[8][4] = {};
        const float* kb = Ks + (j & 1) * BKV * SQ8;
        #pragma unroll
        for (int ks = 0; ks < 8; ++ks) {
            const int k = ks * 8 + tig;
            uint32_t af[4];
            const float* ap = Qs + rq * SQ8 + k;
            af[0] = __float_as_uint(ap[0]);
            af[1] = __float_as_uint(ap[8 * SQ8]);
            af[2] = __float_as_uint(ap[4]);
            af[3] = __float_as_uint(ap[8 * SQ8 + 4]);
            #pragma unroll
            for (int nt = 0; nt < 8; ++nt) {
                const float* bp = kb + (nt * 8 + qid) * SQ8 + k;
                uint32_t bf[2] = {__float_as_uint(bp[0]), __float_as_uint(bp[4])};
                mma_tf32(s[nt], af, bf);
            }
        }

        float mx0 = -1e30f, mx1 = -1e30f;
        #pragma unroll
        for (int nt = 0; nt < 8; ++nt) {
            s[nt][0] *= SCALE_ATTN; s[nt][1] *= SCALE_ATTN;
            s[nt][2] *= SCALE_ATTN; s[nt][3] *= SCALE_ATTN;
            mx0 = fmaxf(mx0, fmaxf(s[nt][0], s[nt][1]));
            mx1 = fmaxf(mx1, fmaxf(s[nt][2], s[nt][3]));
        }
        mx0 = fmaxf(mx0, __shfl_xor_sync(0xffffffffu, mx0, 1));
        mx0 = fmaxf(mx0, __shfl_xor_sync(0xffffffffu, mx0, 2));
        mx1 = fmaxf(mx1, __shfl_xor_sync(0xffffffffu, mx1, 1));
        mx1 = fmaxf(mx1, __shfl_xor_sync(0xffffffffu, mx1, 2));
        const float mn0 = fmaxf(mrow0, mx0), mn1 = fmaxf(mrow1, mx1);
        const float a0 = __expf(mrow0 - mn0), a1 = __expf(mrow1 - mn1);
        mrow0 = mn0; mrow1 = mn1;

        float sum0 = 0.0f, sum1 = 0.0f;
        #pragma unroll
        for (int nt = 0; nt < 8; ++nt) {
            const float p0 = __expf(s[nt][0] - mn0), p1 = __expf(s[nt][1] - mn0);
            const float p2 = __expf(s[nt][2] - mn1), p3 = __expf(s[nt][3] - mn1);
            sum0 += p0 + p1; sum1 += p2 + p3;
            s[nt][0] = rna_tf32(p0); s[nt][1] = rna_tf32(p1);
            s[nt][2] = rna_tf32(p2); s[nt][3] = rna_tf32(p3);
        }
        sum0 += __shfl_xor_sync(0xffffffffu, sum0, 1);
        sum0 += __shfl_xor_sync(0xffffffffu, sum0, 2);
        sum1 += __shfl_xor_sync(0xffffffffu, sum1, 1);
        sum1 += __shfl_xor_sync(0xffffffffu, sum1, 2);
        lrow0 = lrow0 * a0 + sum0;
        lrow1 = lrow1 * a1 + sum1;
        #pragma unroll
        for (int nt = 0; nt < 8; ++nt) {
            o[nt][0] *= a0; o[nt][1] *= a0;
            o[nt][2] *= a1; o[nt][3] *= a1;
        }

        const float* vb = Vs + (j & 1) * HDIM * SQ8;
        #pragma unroll
        for (int kc = 0; kc < 8; ++kc) {
            uint32_t af[4];
            af[0] = __float_as_uint(s[kc][0]);
            af[1] = __float_as_uint(s[kc][2]);
            af[2] = __float_as_uint(s[kc][1]);
            af[3] = __float_as_uint(s[kc][3]);
            const int k = kc * 8 + tig;
            #pragma unroll
            for (int nt = 0; nt < 8; ++nt) {
                const float* bp = vb + (nt * 8 + qid) * SQ8 + k;
                uint32_t bf[2] = {__float_as_uint(bp[0]), __float_as_uint(bp[4])};
                mma_tf32(o[nt], af, bf);
            }
        }
        __syncthreads();
    }

    const float inv0 = 1.0f / lrow0, inv1 = 1.0f / lrow1;
    const int q0 = blockIdx.x * BQ + rq;
    float* dst0 = ctx + ((size_t)b * SEQ + q0) * EMBED + h * HDIM;
    float* dst1 = ctx + ((size_t)b * SEQ + q0 + 8) * EMBED + h * HDIM;
    #pragma unroll
    for (int nt = 0; nt < 8; ++nt) {
        const int d = nt * 8 + tig * 2;
        *(float2*)&dst0[d] = make_float2(rna_tf32(o[nt][0] * inv0),
                                         rna_tf32(o[nt][1] * inv0));
        *(float2*)&dst1[d] = make_float2(rna_tf32(o[nt][2] * inv1),
                                         rna_tf32(o[nt][3] * inv1));
    }
}

// ---------------------------------------------------------------------------
// Launch
// ---------------------------------------------------------------------------
#define SMEM_GEMM  (256 * SA * 4 * 2)                      // 90112 B
#define SMEM_FLASH ((BQ + 2 * BKV + 2 * HDIM) * SQ8 * 4)   // 104448 B -> 2 CTAs/SM

extern "C" void kernel_launch(void* const* d_in, const int* in_sizes, int n_in,
                              void* d_out, int out_size)
{
    (void)in_sizes; (void)n_in; (void)out_size;
    const float* query = (const float*)d_in[0];
    const float* key   = (const float*)d_in[1];
    const float* value = (const float*)d_in[2];
    const float* Wq = (const float*)d_in[3];  const float* bq = (const float*)d_in[4];
    const float* Wk = (const float*)d_in[5];  const float* bk = (const float*)d_in[6];
    const float* Wv = (const float*)d_in[7];  const float* bv = (const float*)d_in[8];
    const float* Wo = (const float*)d_in[9];  const float* bo = (const float*)d_in[10];
    float* out = (float*)d_out;

    float *Wdq, *QK, *Vt, *Cx;
    cudaGetSymbolAddress((void**)&Wdq, g_Wdq);
    cudaGetSymbolAddress((void**)&QK,  g_QK);
    cudaGetSymbolAddress((void**)&Vt,  g_Vt);
    cudaGetSymbolAddress((void**)&Cx,  g_ctx);

    cudaFuncSetAttribute(gemm_proj, cudaFuncAttributeMaxDynamicSharedMemorySize, SMEM_GEMM);
    cudaFuncSetAttribute(gemm_out,  cudaFuncAttributeMaxDynamicSharedMemorySize, SMEM_GEMM);
    cudaFuncSetAttribute(k_flash,   cudaFuncAttributeMaxDynamicSharedMemorySize, SMEM_FLASH);

    // 1) weight quant-dequant (+ tf32 RNA)
    k_reset<<<1, 32>>>();
    k_absmax<<<dim3(256, 4), 256>>>(Wq, Wk, Wv, Wo);
    k_dequant<<<dim3(WELEMS / (256 * 4), 4), 256>>>(Wq, Wk, Wv, Wo);

    // 2) fused Q/K/V projections (A rounded in-kernel; V written transposed)
    gemm_proj<<<dim3(EMBED / 128, TOKENS / 128, 3), 256, SMEM_GEMM>>>(
        query, key, value, bq, bk, bv);

    // 3) fused attention (QK^T + online softmax + PV) -> ctx [B,S,E]
    const size_t qkOff = (size_t)NBATCH * NHEADS * SEQ * HDIM;
    k_flash<<<dim3(SEQ / BQ, 1, NBATCH * NHEADS), 256, SMEM_FLASH>>>(
        QK, QK + qkOff, Vt, Cx);

    // 4) output projection -> d_out
    gemm_out<<<dim3(EMBED / 128, TOKENS / 128, 1), 256, SMEM_GEMM>>>(
        Cx, Wdq + 3 * (size_t)WELEMS, bo, out);
}